// round 7
// baseline (speedup 1.0000x reference)
#include <cuda_runtime.h>
#include <cstdint>
#include <cstddef>

// Fused e3nn per-irrep linear, tf32 mma.sync (sm_103-safe PTX only).
// R7: 512-thread CTAs with tall M-tiles (halve B L2 traffic), BK=32 stages
// (halve barriers), ldmatrix A-fragments, zero in-loop cvt (PWC-compensated),
// cp.async double-buffer with tile-invariant addresses.
//   out[b, off + w*D + i] = PW * sum_u W[u,w] * x[b, off + u*D + i]  (+bias, D==1)

static constexpr int MUL   = 512;
static constexpr int DIM   = 4608;
static constexpr int BATCH = 4096;
static constexpr int BN  = 128;
static constexpr int BK  = 32;
static constexpr int NKT = MUL / BK;        // 16 k-tiles
static constexpr int NT  = 512;             // threads per CTA
// PW * (1 + 2^-10): compensates fp32->tf32 truncation of both operands.
static constexpr float PWC = 0.04423733224f;

static constexpr int LDKB  = 144;           // A row stride bytes (36 floats)
static constexpr int A_REG = 256 * LDKB;    // 36864 (max R = 256)
static constexpr int LDBF  = 136;           // B row stride floats
static constexpr int B_REG = BK * LDBF * 4; // 17408
static constexpr int STAGE = A_REG + B_REG; // 54272
static constexpr int SM_TOTAL = 2 * STAGE;  // 108544

__device__ __forceinline__ void cp16(uint32_t s, const void* g) {
    asm volatile("cp.async.cg.shared.global [%0], [%1], 16;" :: "r"(s), "l"(g));
}
__device__ __forceinline__ void cp4(uint32_t s, const void* g) {
    asm volatile("cp.async.ca.shared.global [%0], [%1], 4;" :: "r"(s), "l"(g));
}
__device__ __forceinline__ void cp_commit() {
    asm volatile("cp.async.commit_group;" ::: "memory");
}
__device__ __forceinline__ void cp_wait1() {
    asm volatile("cp.async.wait_group 1;" ::: "memory");
}
__device__ __forceinline__ void ldmx4(uint32_t& r0, uint32_t& r1, uint32_t& r2,
                                      uint32_t& r3, uint32_t addr) {
    asm volatile("ldmatrix.sync.aligned.m8n8.x4.shared.b16 {%0,%1,%2,%3}, [%4];"
                 : "=r"(r0), "=r"(r1), "=r"(r2), "=r"(r3) : "r"(addr));
}
__device__ __forceinline__ float lds_f(uint32_t addr) {
    float v;
    asm volatile("ld.shared.f32 %0, [%1];" : "=f"(v) : "r"(addr));
    return v;
}
__device__ __forceinline__ void mma_tf32(
    float& c0, float& c1, float& c2, float& c3,
    uint32_t a0, uint32_t a1, uint32_t a2, uint32_t a3,
    uint32_t b0, uint32_t b1)
{
    asm volatile(
        "mma.sync.aligned.m16n8k8.row.col.f32.tf32.tf32.f32 "
        "{%0,%1,%2,%3}, {%4,%5,%6,%7}, {%8,%9}, {%0,%1,%2,%3};"
        : "+f"(c0), "+f"(c1), "+f"(c2), "+f"(c3)
        : "r"(a0), "r"(a1), "r"(a2), "r"(a3), "r"(b0), "r"(b1));
}

template<int D, int R, int NWM, int NWN>
__device__ __forceinline__ void run_tile(
    const float* __restrict__ x, const float* __restrict__ w,
    const float* __restrict__ bias, float* __restrict__ out,
    int mt, int nt, int off, uint32_t smb)
{
    constexpr int BM    = R / D;
    constexpr int WM    = R / NWM;
    constexpr int WN    = BN / NWN;
    constexpr int MFRAG = WM / 16;
    constexpr int NFRAG = WN / 8;
    constexpr int NA    = (D == 1) ? (R * BK / 4 / NT) : (BM * BK * D / NT);
    static_assert(NWM * NWN == 16 && WM % 16 == 0 && WN % 8 == 0, "layout");

    const int tid  = threadIdx.x;
    const int wid  = tid >> 5;
    const int lane = tid & 31;
    const int g    = lane >> 2;
    const int tig  = lane & 3;
    const int wm   = wid % NWM;
    const int wn   = wid / NWM;
    const int b0   = mt * BM;
    const int w0   = nt * BN;

    // ---- tile-invariant fill assignments ----
    const float* const xb = x + (size_t)b0 * DIM + off;
    int      aoffg[NA];
    uint32_t aoffs[NA];
    #pragma unroll
    for (int e = 0; e < NA; e++) {
        const int v = tid + e * NT;
        if constexpr (D == 1) {
            const int r = v >> 3, ch = v & 7;
            aoffg[e] = r * DIM + ch * 4;
            aoffs[e] = (uint32_t)(r * LDKB + ch * 16);
        } else {
            const int bl = v / (BK * D);
            const int j  = v % (BK * D);
            const int k  = j / D;
            const int r  = bl * D + j % D;
            aoffg[e] = bl * DIM + j;
            aoffs[e] = (uint32_t)(r * LDKB + k * 4);
        }
    }
    const float* const wb = w + w0;
    int      boffg[2];
    uint32_t boffs[2];
    #pragma unroll
    for (int e = 0; e < 2; e++) {
        const int v = tid + e * NT;
        const int k = v >> 5, ch = v & 31;
        boffg[e] = k * MUL + ch * 4;
        boffs[e] = (uint32_t)(A_REG + k * LDBF * 4 + ch * 16);
    }
    const int rowadd = (lane & 7) + ((lane >> 3) & 1) * 8;
    const int hi16   = (lane >> 4) * 16;

    float acc[MFRAG][NFRAG][4] = {};

    auto load_tile = [&](int t, uint32_t base) {
        const int ta = t * (BK * D);
        #pragma unroll
        for (int e = 0; e < NA; e++) {
            if constexpr (D == 1) cp16(base + aoffs[e], xb + aoffg[e] + ta);
            else                  cp4 (base + aoffs[e], xb + aoffg[e] + ta);
        }
        const int tb = t * (BK * MUL);
        #pragma unroll
        for (int e = 0; e < 2; e++)
            cp16(base + boffs[e], wb + boffg[e] + tb);
    };

    load_tile(0, smb);
    cp_commit();

    for (int t = 0; t < NKT; t++) {
        const uint32_t Ac = smb + (t & 1) * STAGE;
        const uint32_t Bc = Ac + A_REG;
        if (t + 1 < NKT)
            load_tile(t + 1, smb + ((t + 1) & 1) * STAGE);
        cp_commit();
        cp_wait1();
        __syncthreads();

        #pragma unroll
        for (int kk = 0; kk < BK; kk += 8) {
            uint32_t afr[MFRAG][4];
            #pragma unroll
            for (int m = 0; m < MFRAG; m++) {
                const uint32_t a = Ac + (uint32_t)((wm * WM + m * 16 + rowadd) * LDKB
                                                   + kk * 4 + hi16);
                ldmx4(afr[m][0], afr[m][1], afr[m][2], afr[m][3], a);
            }
            uint32_t bfr[NFRAG][2];
            #pragma unroll
            for (int n = 0; n < NFRAG; n++) {
                const uint32_t f = Bc + (uint32_t)(((kk + tig) * LDBF
                                                   + wn * WN + n * 8 + g) * 4);
                bfr[n][0] = __float_as_uint(lds_f(f));
                bfr[n][1] = __float_as_uint(lds_f(f + 4 * LDBF * 4));
            }
            #pragma unroll
            for (int m = 0; m < MFRAG; m++)
                #pragma unroll
                for (int n = 0; n < NFRAG; n++)
                    mma_tf32(acc[m][n][0], acc[m][n][1], acc[m][n][2], acc[m][n][3],
                             afr[m][0], afr[m][1], afr[m][2], afr[m][3],
                             bfr[n][0], bfr[n][1]);
        }
        __syncthreads();
    }

    // ---- epilogue (truncation compensation folded into PWC) ----
    #pragma unroll
    for (int m = 0; m < MFRAG; m++) {
        #pragma unroll
        for (int half = 0; half < 2; half++) {
            const int row = wm * WM + m * 16 + g + half * 8;
            const int b   = b0 + row / D;
            const int i   = row % D;
            float* orow = out + (size_t)b * DIM + off + i;
            #pragma unroll
            for (int n = 0; n < NFRAG; n++) {
                const int col = wn * WN + n * 8 + 2 * tig;
                #pragma unroll
                for (int e = 0; e < 2; e++) {
                    const int wc = w0 + col + e;
                    float v = acc[m][n][half * 2 + e] * PWC;
                    if (D == 1) v += bias[wc];
                    orow[(size_t)wc * D] = v;
                }
            }
        }
    }
}

// D=1 tile 256x128 -> 16*4 = 64; D=3 192x128 -> 64*4 = 256; D=5 160x128 -> 128*4 = 512
static constexpr int NB0 = (BATCH / 256) * (MUL / BN);          // 64
static constexpr int NB1 = ((BATCH * 3) / 192) * (MUL / BN);    // 256
static constexpr int NB2 = ((BATCH * 5) / 160) * (MUL / BN);    // 512
static constexpr int GRID = NB0 + NB1 + NB2;                    // 832

__global__ __launch_bounds__(NT, 1) void fused_irrep_kernel(
    const float* __restrict__ x,
    const float* __restrict__ w0, const float* __restrict__ w1,
    const float* __restrict__ w2, const float* __restrict__ b0,
    float* __restrict__ out)
{
    extern __shared__ __align__(16) char sm[];
    const uint32_t smb = (uint32_t)__cvta_generic_to_shared(sm);
    const int bx = blockIdx.x;
    if (bx < NB0) {
        run_tile<1, 256, 4, 4>(x, w0, b0, out, bx >> 2, bx & 3, 0, smb);
    } else if (bx < NB0 + NB1) {
        const int i = bx - NB0;
        run_tile<3, 192, 4, 4>(x, w1, b0, out, i >> 2, i & 3, 512, smb);
    } else {
        const int i = bx - NB0 - NB1;
        run_tile<5, 160, 2, 8>(x, w2, b0, out, i >> 2, i & 3, 2048, smb);
    }
}

extern "C" void kernel_launch(void* const* d_in, const int* in_sizes, int n_in,
                              void* d_out, int out_size)
{
    const float* x  = (const float*)d_in[0];
    const float* w0 = (const float*)d_in[1];
    const float* w1 = (const float*)d_in[2];
    const float* w2 = (const float*)d_in[3];
    const float* b0 = (const float*)d_in[4];
    float* out = (float*)d_out;

    cudaFuncSetAttribute(fused_irrep_kernel,
                         cudaFuncAttributeMaxDynamicSharedMemorySize, SM_TOTAL);
    fused_irrep_kernel<<<GRID, NT, SM_TOTAL>>>(x, w0, w1, w2, b0, out);
}